// round 15
// baseline (speedup 1.0000x reference)
#include <cuda_runtime.h>
#include <cstdint>

#define T_STEPS 336
#define BATCH   4096
#define NFEAT   32
#define UN1     64
#define UN2     32
#define G1      256   // 4*UN1
#define G2      128   // 4*UN2
#define ROWS    32
#define THREADS 1024
#define CTAS    (BATCH / ROWS)   // 128
#define RSTRIDE 132   // padded combined row: [x(32)|h1(64)|h2(32)|pad(4)]
#define ROWBASE(r) ((r) * RSTRIDE)
#define BUFSZ (ROWS * RSTRIDE)   // 4224 floats per state buffer

// quad-split interleaved weights (R10/11/13-proven):
//  W1A[k][up] = float4{ w_i(2up), w_i(2up+1), w_f(2up), w_f(2up+1) }, k = 0..95
//  W1B likewise gates g,o. Row stride WK floats.
#define WK1 128
#define WK2 64

// ---- shared memory layout (float offsets) ----
#define OFF_W1A 0
#define OFF_W1B (OFF_W1A + 96 * WK1)            // 12288
#define OFF_W2A (OFF_W1B + 96 * WK1)            // 24576
#define OFF_W2B (OFF_W2A + 96 * WK2)            // 30720
#define OFF_C   (OFF_W2B + 96 * WK2)            // 36864
#define SMEM_FLOATS (OFF_C + 2 * BUFSZ)         // 45312 -> 181248 bytes

typedef unsigned long long ull;

// ---------------- packed f32x2 helpers ----------------
__device__ __forceinline__ ull pack2(float a) {
    ull r; asm("mov.b64 %0, {%1, %1};" : "=l"(r) : "f"(a)); return r;
}
__device__ __forceinline__ ull pakf2(float x, float y) {
    ull r; asm("mov.b64 %0, {%1, %2};" : "=l"(r) : "f"(x), "f"(y)); return r;
}
__device__ __forceinline__ ull fma2(ull a, ull b, ull c) {
    ull d; asm("fma.rn.f32x2 %0, %1, %2, %3;" : "=l"(d) : "l"(a), "l"(b), "l"(c)); return d;
}
__device__ __forceinline__ float2 unpack2(ull v) {
    float2 r; asm("mov.b64 {%0, %1}, %2;" : "=f"(r.x), "=f"(r.y) : "l"(v)); return r;
}

// ---------------- fast HW math ----------------
__device__ __forceinline__ float ex2a(float x) {
    float y; asm("ex2.approx.f32 %0, %1;" : "=f"(y) : "f"(x)); return y;
}
__device__ __forceinline__ float rcpa(float x) {
    float y; asm("rcp.approx.f32 %0, %1;" : "=f"(y) : "f"(x)); return y;
}

// Full LSTM pointwise update, one row (2 units), batched reciprocals (proven):
// 10x EX2 + 2x RCP. Keras gate order i,f,c(g),o.
__device__ __forceinline__ float2 lstm_act2(float2 zi, float2 zf, float2 zg, float2 zo,
                                            float& cc0, float& cc1) {
    const float NL2E  = -1.4426950408889634f;   // -log2(e)
    const float N2L2E = -2.8853900817779268f;   // -2*log2(e)
    float ei0 = ex2a(zi.x * NL2E), ei1 = ex2a(zi.y * NL2E);
    float ef0 = ex2a(zf.x * NL2E), ef1 = ex2a(zf.y * NL2E);
    float eg0 = ex2a(fabsf(zg.x) * N2L2E), eg1 = ex2a(fabsf(zg.y) * N2L2E);
    float eo0 = ex2a(zo.x * NL2E), eo1 = ex2a(zo.y * NL2E);
    float di0 = 1.f + ei0, di1 = 1.f + ei1;
    float df0 = 1.f + ef0, df1 = 1.f + ef1;
    float dg0 = 1.f + eg0, dg1 = 1.f + eg1;
    float do0 = 1.f + eo0, do1 = 1.f + eo1;
    float p01 = di0 * di1, p23 = df0 * df1, p45 = dg0 * dg1, p67 = do0 * do1;
    float q0 = p01 * p23, q1 = p45 * p67;
    float R  = rcpa(q0 * q1);
    float iq0 = R * q1, iq1 = R * q0;
    float ip01 = iq0 * p23, ip23 = iq0 * p01;
    float ip45 = iq1 * p67, ip67 = iq1 * p45;
    float i0 = ip01 * di1, i1 = ip01 * di0;
    float f0 = ip23 * df1, f1 = ip23 * df0;
    float go0 = ip45 * dg1, go1 = ip45 * dg0;
    float o0 = ip67 * do1, o1 = ip67 * do0;
    float tg0 = copysignf((1.f - eg0) * go0, zg.x);
    float tg1 = copysignf((1.f - eg1) * go1, zg.y);
    cc0 = f0 * cc0 + i0 * tg0;
    cc1 = f1 * cc1 + i1 * tg1;
    float ec0 = ex2a(fabsf(cc0) * N2L2E), ec1 = ex2a(fabsf(cc1) * N2L2E);
    float dc0 = 1.f + ec0, dc1 = 1.f + ec1;
    float Rc = rcpa(dc0 * dc1);
    float tc0 = copysignf((1.f - ec0) * (Rc * dc1), cc0);
    float tc1 = copysignf((1.f - ec1) * (Rc * dc0), cc1);
    float2 h; h.x = o0 * tc0; h.y = o1 * tc1;
    return h;
}

// ---------------- cp.async helpers ----------------
__device__ __forceinline__ void cp16(uint32_t saddr, const float* g) {
    asm volatile("cp.async.cg.shared.global [%0], [%1], 16;" :: "r"(saddr), "l"(g));
}
__device__ __forceinline__ void cp_commit() { asm volatile("cp.async.commit_group;"); }
__device__ __forceinline__ void cp_wait0()  { asm volatile("cp.async.wait_group 0;" ::: "memory"); }

// Full-K (96) panel: R rows (independent base pointers) x (2 units x 4 gates).
// Weights read once per CTA-step; 2x LDS.128 per k; float4 inputs.
template <int R, int WK>
__device__ __forceinline__ void panelFull(ull (&acc)[R][4],
                                          const float* const (&in)[R],
                                          const float* wA, const float* wB) {
#pragma unroll 2
    for (int k = 0; k < 96; k += 4) {
        float4 a[R];
#pragma unroll
        for (int r = 0; r < R; r++) a[r] = *(const float4*)(in[r] + k);
#pragma unroll
        for (int kk = 0; kk < 4; kk++) {
            ulonglong2 qa = *(const ulonglong2*)(wA + (k + kk) * WK);
            ulonglong2 qb = *(const ulonglong2*)(wB + (k + kk) * WK);
#pragma unroll
            for (int r = 0; r < R; r++) {
                float av = (kk == 0) ? a[r].x : (kk == 1) ? a[r].y : (kk == 2) ? a[r].z : a[r].w;
                ull p = pack2(av);
                acc[r][0] = fma2(p, qa.x, acc[r][0]);
                acc[r][1] = fma2(p, qa.y, acc[r][1]);
                acc[r][2] = fma2(p, qb.x, acc[r][2]);
                acc[r][3] = fma2(p, qb.y, acc[r][3]);
            }
        }
    }
}

__global__ void __launch_bounds__(THREADS, 1)
lstm_fused_kernel(const float* __restrict__ x,
                  const float* __restrict__ W1, const float* __restrict__ U1w, const float* __restrict__ b1,
                  const float* __restrict__ W2, const float* __restrict__ U2w, const float* __restrict__ b2,
                  const float* __restrict__ Wv, const float* __restrict__ bv,
                  const float* __restrict__ Wo, const float* __restrict__ bo,
                  const float* __restrict__ Wd1, const float* __restrict__ bd1,
                  const float* __restrict__ Wd2, const float* __restrict__ bd2,
                  float* __restrict__ out) {
    extern __shared__ float sm[];
    const int tid = threadIdx.x;
    const int b0  = blockIdx.x * ROWS;

    // ---- stage weights into quad-split interleaved SMEM arrays ----
    for (int idx = tid; idx < 96 * 32; idx += THREADS) {
        int k = idx >> 5, u = idx & 31;
        const float* src = (k < NFEAT) ? (W1 + k * G1) : (U1w + (k - NFEAT) * G1);
        float4 qa = make_float4(src[2 * u], src[2 * u + 1],
                                src[UN1 + 2 * u], src[UN1 + 2 * u + 1]);
        float4 qb = make_float4(src[2 * UN1 + 2 * u], src[2 * UN1 + 2 * u + 1],
                                src[3 * UN1 + 2 * u], src[3 * UN1 + 2 * u + 1]);
        ((float4*)(sm + OFF_W1A))[k * 32 + u] = qa;
        ((float4*)(sm + OFF_W1B))[k * 32 + u] = qb;
    }
    for (int idx = tid; idx < 96 * 16; idx += THREADS) {
        int k = idx >> 4, u = idx & 15;
        const float* src = (k < UN1) ? (W2 + k * G2) : (U2w + (k - UN1) * G2);
        float4 qa = make_float4(src[2 * u], src[2 * u + 1],
                                src[UN2 + 2 * u], src[UN2 + 2 * u + 1]);
        float4 qb = make_float4(src[2 * UN2 + 2 * u], src[2 * UN2 + 2 * u + 1],
                                src[3 * UN2 + 2 * u], src[3 * UN2 + 2 * u + 1]);
        ((float4*)(sm + OFF_W2A))[k * 16 + u] = qa;
        ((float4*)(sm + OFF_W2B))[k * 16 + u] = qb;
    }
    for (int i = tid; i < 2 * BUFSZ; i += THREADS) sm[OFF_C + i] = 0.0f;

    // ---- unit-sliced mapping, 32 warps ----
    // warps 0-15  = L1: warp w owns ups {2w, 2w+1}; thread = 2 rows x 1 up
    // warps 16-31 = L2: warp w-16 owns up2 = w-16; thread = 1 row x 1 up
    const int wid = tid >> 5;
    const int l   = tid & 31;
    const bool isL1 = (wid < 16);
    const int up  = (wid << 1) | (l & 1);   // L1 unit pair 0..31
    const int rg  = l >> 1;                 // L1: rows rg*2, rg*2+1
    const int up2 = wid - 16;               // L2 unit pair 0..15 (warp-uniform)
    const int r2  = l;                      // L2 row 0..31

    // full bias in registers for every lane
    ull bq[4];
    if (isL1) {
#pragma unroll
        for (int g = 0; g < 4; g++) {
            float2 bb = *(const float2*)(b1 + g * UN1 + 2 * up);
            bq[g] = pakf2(bb.x, bb.y);
        }
    } else {
#pragma unroll
        for (int g = 0; g < 4; g++) {
            float2 bb = *(const float2*)(b2 + g * UN2 + 2 * up2);
            bq[g] = pakf2(bb.x, bb.y);
        }
    }

    float c1[2][2], c2[2];
    c1[0][0] = c1[0][1] = c1[1][0] = c1[1][1] = 0.0f;
    c2[0] = c2[1] = 0.0f;

    // ---- x prefetch: movers = warps 16-23 (256 threads), one float4/step ----
    const bool xmover = (wid >= 16 && wid < 24);
    const int m    = ((wid - 16) << 5) | l;   // 0..255
    const int mrow = m >> 3;                  // 0..31
    const int mq   = m & 7;                   // 0..7
    const float* xg = x + ((size_t)(b0 + mrow) * T_STEPS) * NFEAT + mq * 4;
    uint32_t sx0 = (uint32_t)__cvta_generic_to_shared(sm + OFF_C + ROWBASE(mrow) + mq * 4);
    const uint32_t cbufbytes = BUFSZ * 4;

    __syncthreads();                    // staging visible before cp.async writes x
    if (xmover) { cp16(sx0, xg); cp_commit(); }

    const float* wA1 = sm + OFF_W1A + up * 4;
    const float* wB1 = sm + OFF_W1B + up * 4;
    const float* wA2 = sm + OFF_W2A + up2 * 4;
    const float* wB2 = sm + OFF_W2B + up2 * 4;

    // Iter t: L1 computes step t (t<T), L2 computes step t-1 (t>=1).
    // Single CTA-wide barrier per step.
    for (int t = 0; t <= T_STEPS; ++t) {
        if (xmover && t < T_STEPS) cp_wait0();
        __syncthreads();
        if (xmover && t + 1 < T_STEPS) {
            cp16(sx0 + ((t + 1) & 1) * cbufbytes, xg + (size_t)(t + 1) * NFEAT);
            cp_commit();
        }
        const int rb = t & 1;
        const float* cin  = sm + OFF_C + rb * BUFSZ;
        float*       cout = sm + OFF_C + (rb ^ 1) * BUFSZ;

        if (isL1) {
            if (t < T_STEPS) {
                ull acc[2][4];
#pragma unroll
                for (int r = 0; r < 2; r++)
#pragma unroll
                    for (int g = 0; g < 4; g++) acc[r][g] = bq[g];

                const float* in[2] = { cin + ROWBASE(rg * 2),
                                       cin + ROWBASE(rg * 2 + 1) };
                panelFull<2, WK1>(acc, in, wA1, wB1);   // gate K-rows [x|h1] cols 0..95

#pragma unroll
                for (int r = 0; r < 2; r++) {
                    float2 h = lstm_act2(unpack2(acc[r][0]), unpack2(acc[r][1]),
                                         unpack2(acc[r][2]), unpack2(acc[r][3]),
                                         c1[r][0], c1[r][1]);
                    *(float2*)(cout + ROWBASE(rg * 2 + r) + 32 + 2 * up) = h;   // h1(t)
                }
            }
        } else {
            if (t >= 1) {
                ull acc2[1][4];
#pragma unroll
                for (int g = 0; g < 4; g++) acc2[0][g] = bq[g];

                const float* in2[1] = { cin + ROWBASE(r2) + 32 };
                panelFull<1, WK2>(acc2, in2, wA2, wB2); // [h1(t-1)|h2(t-2)] cols 32..127

                float2 h = lstm_act2(unpack2(acc2[0][0]), unpack2(acc2[0][1]),
                                     unpack2(acc2[0][2]), unpack2(acc2[0][3]),
                                     c2[0], c2[1]);
                *(float2*)(cout + ROWBASE(r2) + 96 + 2 * up2) = h;              // h2(t-1)
            }
        }
    }
    __syncthreads();

    // final h2 = h2(T-1), written at iter t=T into buf ((T&1)^1)
    const float* h2f = sm + OFF_C + ((T_STEPS & 1) ^ 1) * BUFSZ;

    // ============ head: MHA(seq=1) == identity-attention -> v@Wo, then MLP ============
    float* sv  = sm;            // scratch in dead weight region
    float* so  = sm + 1024;
    float* sd1 = sm + 2048;
    for (int idx = tid; idx < ROWS * 32; idx += THREADS) {
        int r = idx >> 5, j = idx & 31;
        float s = bv[j];
        const float* h2row = h2f + ROWBASE(r) + 96;
#pragma unroll
        for (int d = 0; d < 32; d++) s += h2row[d] * Wv[d * 32 + j];
        sv[idx] = s;
    }
    __syncthreads();
    for (int idx = tid; idx < ROWS * 32; idx += THREADS) {
        int r = idx >> 5, e = idx & 31;
        float s = bo[e];
#pragma unroll
        for (int j = 0; j < 32; j++) s += sv[r * 32 + j] * Wo[j * 32 + e];
        so[idx] = s;
    }
    __syncthreads();
    for (int idx = tid; idx < ROWS * 64; idx += THREADS) {
        int r = idx >> 6, mm = idx & 63;
        float s = bd1[mm];
#pragma unroll
        for (int e = 0; e < 32; e++) s += so[r * 32 + e] * Wd1[e * 64 + mm];
        sd1[idx] = fmaxf(s, 0.0f);
    }
    __syncthreads();
    for (int idx = tid; idx < ROWS * 24; idx += THREADS) {
        int r = idx / 24, p = idx % 24;
        float s = bd2[p];
#pragma unroll
        for (int mm = 0; mm < 64; mm++) s += sd1[r * 64 + mm] * Wd2[mm * 24 + p];
        out[(size_t)(b0 + r) * 24 + p] = s;
    }
}

extern "C" void kernel_launch(void* const* d_in, const int* in_sizes, int n_in,
                              void* d_out, int out_size) {
    const float* x   = (const float*)d_in[0];
    const float* W1  = (const float*)d_in[1];
    const float* U1w = (const float*)d_in[2];
    const float* b1  = (const float*)d_in[3];
    const float* W2  = (const float*)d_in[4];
    const float* U2w = (const float*)d_in[5];
    const float* b2  = (const float*)d_in[6];
    // d_in[7..10] = Wq, bq, Wk, bk: dead (softmax over seq-len 1 == 1)
    const float* Wv  = (const float*)d_in[11];
    const float* bv  = (const float*)d_in[12];
    const float* Wo  = (const float*)d_in[13];
    const float* bo  = (const float*)d_in[14];
    const float* Wd1 = (const float*)d_in[15];
    const float* bd1 = (const float*)d_in[16];
    const float* Wd2 = (const float*)d_in[17];
    const float* bd2 = (const float*)d_in[18];

    size_t smem = SMEM_FLOATS * sizeof(float);   // 181248 B
    cudaFuncSetAttribute(lstm_fused_kernel,
                         cudaFuncAttributeMaxDynamicSharedMemorySize, (int)smem);
    lstm_fused_kernel<<<CTAS, THREADS, smem>>>(
        x, W1, U1w, b1, W2, U2w, b2, Wv, bv, Wo, bo, Wd1, bd1, Wd2, bd2,
        (float*)d_out);
}

// round 16
// speedup vs baseline: 1.1568x; 1.1568x over previous
#include <cuda_runtime.h>
#include <cuda_fp16.h>
#include <cstdint>

#define T_STEPS 336
#define BATCH   4096
#define NFEAT   32
#define UN1     64
#define UN2     32
#define G1      256   // 4*UN1
#define G2      128   // 4*UN2
#define ROWS    32
#define THREADS 512
#define CTAS    (BATCH / ROWS)   // 128
#define RSTRIDE 128   // combined row: [x(32)|h1(64)|h2(32)]
// R13-proven injective row swizzle
#define ROWBASE(r) ((r) * RSTRIDE + ((((r) >> 2) & 7) << 2))
#define BUFSZ (ROWS * RSTRIDE + 32)   // 4128 floats per state buffer

// quad-split interleaved weights (proven):
//  W1A[k][up] = float4{ w_i(2up), w_i(2up+1), w_f(2up), w_f(2up+1) }, k = 0..95
//  W1B likewise gates g,o. Row stride WK floats.
#define WK1 128
#define WK2 64

// xw1 staging: fp16x2 per (row, gate, up): addr = row*XWS + g*32 + up (uints)
#define XWS 129
#define XWBUF (ROWS * XWS)    // 4128 uints per buffer

// ---- shared memory layout (float/uint offsets, both 4B) ----
#define OFF_W1A 0
#define OFF_W1B (OFF_W1A + 96 * WK1)            // 12288
#define OFF_W2A (OFF_W1B + 96 * WK1)            // 24576
#define OFF_W2B (OFF_W2A + 96 * WK2)            // 30720
#define OFF_C   (OFF_W2B + 96 * WK2)            // 36864
#define OFF_XW  (OFF_C + 2 * BUFSZ)             // 45120
#define SMEM_FLOATS (OFF_XW + 2 * XWBUF)        // 53376 -> 213504 bytes

typedef unsigned long long ull;

// ---------------- packed f32x2 helpers ----------------
__device__ __forceinline__ ull pack2(float a) {
    ull r; asm("mov.b64 %0, {%1, %1};" : "=l"(r) : "f"(a)); return r;
}
__device__ __forceinline__ ull pakf2(float x, float y) {
    ull r; asm("mov.b64 %0, {%1, %2};" : "=l"(r) : "f"(x), "f"(y)); return r;
}
__device__ __forceinline__ ull fma2(ull a, ull b, ull c) {
    ull d; asm("fma.rn.f32x2 %0, %1, %2, %3;" : "=l"(d) : "l"(a), "l"(b), "l"(c)); return d;
}
__device__ __forceinline__ float2 unpack2(ull v) {
    float2 r; asm("mov.b64 {%0, %1}, %2;" : "=f"(r.x), "=f"(r.y) : "l"(v)); return r;
}

// ---------------- fast HW math ----------------
__device__ __forceinline__ float ex2a(float x) {
    float y; asm("ex2.approx.f32 %0, %1;" : "=f"(y) : "f"(x)); return y;
}
__device__ __forceinline__ float rcpa(float x) {
    float y; asm("rcp.approx.f32 %0, %1;" : "=f"(y) : "f"(x)); return y;
}

// Full LSTM pointwise update, one row (2 units), batched reciprocals (proven).
__device__ __forceinline__ float2 lstm_act2(float2 zi, float2 zf, float2 zg, float2 zo,
                                            float& cc0, float& cc1) {
    const float NL2E  = -1.4426950408889634f;
    const float N2L2E = -2.8853900817779268f;
    float ei0 = ex2a(zi.x * NL2E), ei1 = ex2a(zi.y * NL2E);
    float ef0 = ex2a(zf.x * NL2E), ef1 = ex2a(zf.y * NL2E);
    float eg0 = ex2a(fabsf(zg.x) * N2L2E), eg1 = ex2a(fabsf(zg.y) * N2L2E);
    float eo0 = ex2a(zo.x * NL2E), eo1 = ex2a(zo.y * NL2E);
    float di0 = 1.f + ei0, di1 = 1.f + ei1;
    float df0 = 1.f + ef0, df1 = 1.f + ef1;
    float dg0 = 1.f + eg0, dg1 = 1.f + eg1;
    float do0 = 1.f + eo0, do1 = 1.f + eo1;
    float p01 = di0 * di1, p23 = df0 * df1, p45 = dg0 * dg1, p67 = do0 * do1;
    float q0 = p01 * p23, q1 = p45 * p67;
    float R  = rcpa(q0 * q1);
    float iq0 = R * q1, iq1 = R * q0;
    float ip01 = iq0 * p23, ip23 = iq0 * p01;
    float ip45 = iq1 * p67, ip67 = iq1 * p45;
    float i0 = ip01 * di1, i1 = ip01 * di0;
    float f0 = ip23 * df1, f1 = ip23 * df0;
    float go0 = ip45 * dg1, go1 = ip45 * dg0;
    float o0 = ip67 * do1, o1 = ip67 * do0;
    float tg0 = copysignf((1.f - eg0) * go0, zg.x);
    float tg1 = copysignf((1.f - eg1) * go1, zg.y);
    cc0 = f0 * cc0 + i0 * tg0;
    cc1 = f1 * cc1 + i1 * tg1;
    float ec0 = ex2a(fabsf(cc0) * N2L2E), ec1 = ex2a(fabsf(cc1) * N2L2E);
    float dc0 = 1.f + ec0, dc1 = 1.f + ec1;
    float Rc = rcpa(dc0 * dc1);
    float tc0 = copysignf((1.f - ec0) * (Rc * dc1), cc0);
    float tc1 = copysignf((1.f - ec1) * (Rc * dc0), cc1);
    float2 h; h.x = o0 * tc0; h.y = o1 * tc1;
    return h;
}

// ---------------- cp.async helpers ----------------
__device__ __forceinline__ void cp16(uint32_t saddr, const float* g) {
    asm volatile("cp.async.cg.shared.global [%0], [%1], 16;" :: "r"(saddr), "l"(g));
}
__device__ __forceinline__ void cp_commit() { asm volatile("cp.async.commit_group;"); }
__device__ __forceinline__ void cp_wait0()  { asm volatile("cp.async.wait_group 0;" ::: "memory"); }

// K-column panel: R rows x (2 units x 4 gates), quad-split weights.
template <int R, int K, int WK>
__device__ __forceinline__ void panelK(ull (&acc)[R][4],
                                       const float* const (&in)[R],
                                       const float* wA, const float* wB) {
#pragma unroll 2
    for (int k = 0; k < K; k += 4) {
        float4 a[R];
#pragma unroll
        for (int r = 0; r < R; r++) a[r] = *(const float4*)(in[r] + k);
#pragma unroll
        for (int kk = 0; kk < 4; kk++) {
            ulonglong2 qa = *(const ulonglong2*)(wA + (k + kk) * WK);
            ulonglong2 qb = *(const ulonglong2*)(wB + (k + kk) * WK);
#pragma unroll
            for (int r = 0; r < R; r++) {
                float av = (kk == 0) ? a[r].x : (kk == 1) ? a[r].y : (kk == 2) ? a[r].z : a[r].w;
                ull p = pack2(av);
                acc[r][0] = fma2(p, qa.x, acc[r][0]);
                acc[r][1] = fma2(p, qa.y, acc[r][1]);
                acc[r][2] = fma2(p, qb.x, acc[r][2]);
                acc[r][3] = fma2(p, qb.y, acc[r][3]);
            }
        }
    }
}

__global__ void __launch_bounds__(THREADS, 1)
lstm_fused_kernel(const float* __restrict__ x,
                  const float* __restrict__ W1, const float* __restrict__ U1w, const float* __restrict__ b1,
                  const float* __restrict__ W2, const float* __restrict__ U2w, const float* __restrict__ b2,
                  const float* __restrict__ Wv, const float* __restrict__ bv,
                  const float* __restrict__ Wo, const float* __restrict__ bo,
                  const float* __restrict__ Wd1, const float* __restrict__ bd1,
                  const float* __restrict__ Wd2, const float* __restrict__ bd2,
                  float* __restrict__ out) {
    extern __shared__ float sm[];
    unsigned* xw = (unsigned*)(sm + OFF_XW);
    const int tid = threadIdx.x;
    const int b0  = blockIdx.x * ROWS;

    // ---- stage weights (quad-split interleaved, proven) ----
    for (int idx = tid; idx < 96 * 32; idx += THREADS) {
        int k = idx >> 5, u = idx & 31;
        const float* src = (k < NFEAT) ? (W1 + k * G1) : (U1w + (k - NFEAT) * G1);
        float4 qa = make_float4(src[2 * u], src[2 * u + 1],
                                src[UN1 + 2 * u], src[UN1 + 2 * u + 1]);
        float4 qb = make_float4(src[2 * UN1 + 2 * u], src[2 * UN1 + 2 * u + 1],
                                src[3 * UN1 + 2 * u], src[3 * UN1 + 2 * u + 1]);
        ((float4*)(sm + OFF_W1A))[k * 32 + u] = qa;
        ((float4*)(sm + OFF_W1B))[k * 32 + u] = qb;
    }
    for (int idx = tid; idx < 96 * 16; idx += THREADS) {
        int k = idx >> 4, u = idx & 15;
        const float* src = (k < UN1) ? (W2 + k * G2) : (U2w + (k - UN1) * G2);
        float4 qa = make_float4(src[2 * u], src[2 * u + 1],
                                src[UN2 + 2 * u], src[UN2 + 2 * u + 1]);
        float4 qb = make_float4(src[2 * UN2 + 2 * u], src[2 * UN2 + 2 * u + 1],
                                src[3 * UN2 + 2 * u], src[3 * UN2 + 2 * u + 1]);
        ((float4*)(sm + OFF_W2A))[k * 16 + u] = qa;
        ((float4*)(sm + OFF_W2B))[k * 16 + u] = qb;
    }
    for (int i = tid; i < 2 * BUFSZ; i += THREADS) sm[OFF_C + i] = 0.0f;

    // ---- mapping (R13): warps 0-7 = L1 unit-sliced; warps 8-15 = L2 + xw1 producers ----
    const int wid = tid >> 5;
    const int l   = tid & 31;
    const bool isL1 = (wid < 8);
    const int up  = (wid << 2) | (l & 3);       // L1 unit pair 0..31
    const int rg  = l >> 2;                     // L1 rows rg*4..+3
    const int up2 = ((wid - 8) << 1) | (l & 1); // L2 unit pair 0..15
    const int rg2 = l >> 1;                     // L2 rows rg2*2..+1
    // producer mapping (L2 warps, mirrors L1 shape over W1 x-rows)
    const int upp = ((wid - 8) << 2) | (l & 3); // producer unit pair 0..31
    const int rgp = l >> 2;                     // producer rows rgp*4..+3

    // biases in registers: L2 warps carry b2 (own gates) AND b1 (producer role)
    ull bq[4], bp1[4];
    if (!isL1) {
#pragma unroll
        for (int g = 0; g < 4; g++) {
            float2 v2 = *(const float2*)(b2 + g * UN2 + 2 * up2);
            float2 v1 = *(const float2*)(b1 + g * UN1 + 2 * upp);
            bq[g]  = pakf2(v2.x, v2.y);
            bp1[g] = pakf2(v1.x, v1.y);
        }
    }

    float c1[4][2], c2[2][2];
#pragma unroll
    for (int r = 0; r < 4; r++) { c1[r][0] = c1[r][1] = 0.0f; }
#pragma unroll
    for (int r = 0; r < 2; r++) { c2[r][0] = c2[r][1] = 0.0f; }

    // ---- x prefetch: movers = warps 8-11; 2 float4 per thread per step ----
    const bool xmover = (wid >= 8 && wid < 12);
    const int m    = ((wid - 8) << 5) | l;     // 0..127
    const int mrow = m >> 2;                   // 0..31
    const int mq   = (m & 3) << 1;             // 0,2,4,6
    const float* xg = x + ((size_t)(b0 + mrow) * T_STEPS) * NFEAT + mq * 4;
    uint32_t sx0 = (uint32_t)__cvta_generic_to_shared(sm + OFF_C + ROWBASE(mrow) + mq * 4);
    const uint32_t cbufbytes = BUFSZ * 4;

    const float* wA1h = sm + OFF_W1A + 32 * WK1 + up * 4;   // U1 rows (k=32..95)
    const float* wB1h = sm + OFF_W1B + 32 * WK1 + up * 4;
    const float* wA1x = sm + OFF_W1A + upp * 4;             // W1 x-rows (k=0..31)
    const float* wB1x = sm + OFF_W1B + upp * 4;
    const float* wA2 = sm + OFF_W2A + up2 * 4;
    const float* wB2 = sm + OFF_W2B + up2 * 4;

    __syncthreads();                            // staging visible
    if (xmover) { cp16(sx0, xg); cp16(sx0 + 16, xg + 4); cp_commit(); }
    if (xmover) cp_wait0();
    __syncthreads();                            // x_0 visible to producers

    // ---- prologue: producers compute xw1(0) into xw buf 0 ----
    if (!isL1) {
#pragma unroll
        for (int p = 0; p < 2; p++) {
            ull accp[2][4];
#pragma unroll
            for (int r = 0; r < 2; r++)
#pragma unroll
                for (int g = 0; g < 4; g++) accp[r][g] = bp1[g];
            const float* inp[2] = { sm + OFF_C + ROWBASE(rgp * 4 + 2 * p),
                                    sm + OFF_C + ROWBASE(rgp * 4 + 2 * p + 1) };
            panelK<2, 32, WK1>(accp, inp, wA1x, wB1x);
#pragma unroll
            for (int r = 0; r < 2; r++)
#pragma unroll
                for (int g = 0; g < 4; g++) {
                    float2 f = unpack2(accp[r][g]);
                    *(__half2*)(xw + (rgp * 4 + 2 * p + r) * XWS + g * 32 + upp) =
                        __floats2half2_rn(f.x, f.y);
                }
        }
    }
    if (xmover) {   // issue x_1
        cp16(sx0 + cbufbytes, xg + NFEAT); cp16(sx0 + cbufbytes + 16, xg + NFEAT + 4);
        cp_commit();
    }

    // Iter t: L1 step t (t<T) using xw1(t); L2 step t-1 (t>=1); producers xw1(t+1).
    for (int t = 0; t <= T_STEPS; ++t) {
        if (xmover) cp_wait0();        // x_{t+1} complete (issued at t-1 / prologue)
        __syncthreads();               // publishes xw1(t), h-state, x_{t+1}
        if (xmover && t + 2 < T_STEPS) {   // x_{t+2} -> buf t&1 x-region (dead)
            uint32_t dst = sx0 + (t & 1) * cbufbytes;
            const float* src = xg + (size_t)(t + 2) * NFEAT;
            cp16(dst, src); cp16(dst + 16, src + 4);
            cp_commit();
        }
        const int rb = t & 1;
        const float* cin  = sm + OFF_C + rb * BUFSZ;
        float*       cout = sm + OFF_C + (rb ^ 1) * BUFSZ;

        if (isL1) {
            if (t < T_STEPS) {
                ull acc[4][4];
                const unsigned* xwr = xw + rb * XWBUF;
#pragma unroll
                for (int r = 0; r < 4; r++)
#pragma unroll
                    for (int g = 0; g < 4; g++) {
                        float2 f = __half22float2(
                            *(const __half2*)(xwr + (rg * 4 + r) * XWS + g * 32 + up));
                        acc[r][g] = pakf2(f.x, f.y);
                    }
                const float* in[4] = { cin + ROWBASE(rg * 4) + 32,
                                       cin + ROWBASE(rg * 4 + 1) + 32,
                                       cin + ROWBASE(rg * 4 + 2) + 32,
                                       cin + ROWBASE(rg * 4 + 3) + 32 };
                panelK<4, 64, WK1>(acc, in, wA1h, wB1h);   // recurrent h1 panel only
#pragma unroll
                for (int r = 0; r < 4; r++) {
                    float2 h = lstm_act2(unpack2(acc[r][0]), unpack2(acc[r][1]),
                                         unpack2(acc[r][2]), unpack2(acc[r][3]),
                                         c1[r][0], c1[r][1]);
                    *(float2*)(cout + ROWBASE(rg * 4 + r) + 32 + 2 * up) = h;   // h1(t)
                }
            }
        } else {
            if (t >= 1) {
                ull acc2[2][4];
#pragma unroll
                for (int r = 0; r < 2; r++)
#pragma unroll
                    for (int g = 0; g < 4; g++) acc2[r][g] = bq[g];
                const float* in2[2] = { cin + ROWBASE(rg2 * 2) + 32,
                                        cin + ROWBASE(rg2 * 2 + 1) + 32 };
                panelK<2, 96, WK2>(acc2, in2, wA2, wB2);   // [h1(t-1)|h2(t-2)]
#pragma unroll
                for (int r = 0; r < 2; r++) {
                    float2 h = lstm_act2(unpack2(acc2[r][0]), unpack2(acc2[r][1]),
                                         unpack2(acc2[r][2]), unpack2(acc2[r][3]),
                                         c2[r][0], c2[r][1]);
                    *(float2*)(cout + ROWBASE(rg2 * 2 + r) + 96 + 2 * up2) = h; // h2(t-1)
                }
            }
            if (t + 1 < T_STEPS) {
                // producer: xw1(t+1) from x_{t+1} (cout x cols) -> xw buf (t+1)&1
                unsigned* xww = xw + (rb ^ 1) * XWBUF;
#pragma unroll
                for (int p = 0; p < 2; p++) {
                    ull accp[2][4];
#pragma unroll
                    for (int r = 0; r < 2; r++)
#pragma unroll
                        for (int g = 0; g < 4; g++) accp[r][g] = bp1[g];
                    const float* inp[2] = { cout + ROWBASE(rgp * 4 + 2 * p),
                                            cout + ROWBASE(rgp * 4 + 2 * p + 1) };
                    panelK<2, 32, WK1>(accp, inp, wA1x, wB1x);
#pragma unroll
                    for (int r = 0; r < 2; r++)
#pragma unroll
                        for (int g = 0; g < 4; g++) {
                            float2 f = unpack2(accp[r][g]);
                            *(__half2*)(xww + (rgp * 4 + 2 * p + r) * XWS + g * 32 + upp) =
                                __floats2half2_rn(f.x, f.y);
                        }
                }
            }
        }
    }
    __syncthreads();

    // final h2 = h2(T-1), written at iter t=T into buf ((T&1)^1)
    const float* h2f = sm + OFF_C + ((T_STEPS & 1) ^ 1) * BUFSZ;

    // ============ head: MHA(seq=1) == identity-attention -> v@Wo, then MLP ============
    float* sv  = sm;            // scratch in dead weight region
    float* so  = sm + 1024;
    float* sd1 = sm + 2048;
    for (int idx = tid; idx < ROWS * 32; idx += THREADS) {
        int r = idx >> 5, j = idx & 31;
        float s = bv[j];
        const float* h2row = h2f + ROWBASE(r) + 96;
#pragma unroll
        for (int d = 0; d < 32; d++) s += h2row[d] * Wv[d * 32 + j];
        sv[idx] = s;
    }
    __syncthreads();
    for (int idx = tid; idx < ROWS * 32; idx += THREADS) {
        int r = idx >> 5, e = idx & 31;
        float s = bo[e];
#pragma unroll
        for (int j = 0; j < 32; j++) s += sv[r * 32 + j] * Wo[j * 32 + e];
        so[idx] = s;
    }
    __syncthreads();
    for (int idx = tid; idx < ROWS * 64; idx += THREADS) {
        int r = idx >> 6, mm = idx & 63;
        float s = bd1[mm];
#pragma unroll
        for (int e = 0; e < 32; e++) s += so[r * 32 + e] * Wd1[e * 64 + mm];
        sd1[idx] = fmaxf(s, 0.0f);
    }
    __syncthreads();
    for (int idx = tid; idx < ROWS * 24; idx += THREADS) {
        int r = idx / 24, p = idx % 24;
        float s = bd2[p];
#pragma unroll
        for (int mm = 0; mm < 64; mm++) s += sd1[r * 64 + mm] * Wd2[mm * 24 + p];
        out[(size_t)(b0 + r) * 24 + p] = s;
    }
}

extern "C" void kernel_launch(void* const* d_in, const int* in_sizes, int n_in,
                              void* d_out, int out_size) {
    const float* x   = (const float*)d_in[0];
    const float* W1  = (const float*)d_in[1];
    const float* U1w = (const float*)d_in[2];
    const float* b1  = (const float*)d_in[3];
    const float* W2  = (const float*)d_in[4];
    const float* U2w = (const float*)d_in[5];
    const float* b2  = (const float*)d_in[6];
    // d_in[7..10] = Wq, bq, Wk, bk: dead (softmax over seq-len 1 == 1)
    const float* Wv  = (const float*)d_in[11];
    const float* bv  = (const float*)d_in[12];
    const float* Wo  = (const float*)d_in[13];
    const float* bo  = (const float*)d_in[14];
    const float* Wd1 = (const float*)d_in[15];
    const float* bd1 = (const float*)d_in[16];
    const float* Wd2 = (const float*)d_in[17];
    const float* bd2 = (const float*)d_in[18];

    size_t smem = SMEM_FLOATS * sizeof(float);   // 213504 B
    cudaFuncSetAttribute(lstm_fused_kernel,
                         cudaFuncAttributeMaxDynamicSharedMemorySize, (int)smem);
    lstm_fused_kernel<<<CTAS, THREADS, smem>>>(
        x, W1, U1w, b1, W2, U2w, b2, Wv, bv, Wo, bo, Wd1, bd1, Wd2, bd2,
        (float*)d_out);
}